// round 14
// baseline (speedup 1.0000x reference)
#include <cuda_runtime.h>

#define G       37
#define NPATCH  (G * G)          // 1369
#define D       768
#define NCUE    5
#define STOK    (NCUE + NPATCH)  // 1374
#define BATCH   128
#define EPSN    1e-12f

#define TPB     128              // 1 patch per thread
#define PTILE   128
#define NTILE   11               // ceil(1369/128)
#define N_AM    (NTILE * BATCH)  // 1408 argmax items
#define N_ROI   (BATCH * NCUE)   // 640 ROI-token items
#define NITEMS_ALL (N_AM + N_ROI)
#define NBLK    592              // 4 blocks/SM x 148 SMs, persistent
#define DC      16               // dims per pipeline stage
#define NS      (D / DC)         // 48 stages (NS % NBUF == 0: seamless ring)
#define NBUF    4                // 4-deep ring, 3 stages in flight
#define F4ROW   (DC / 4)         // 4 float4 per row-stage
#define STAGE_F4 (PTILE * F4ROW) // 512 float4 = 8KB per buffer
#define STAGE_B  (STAGE_F4 * 16) // 8192

// Cross-item scratch. All reset in-kernel (ROI items reset their g_best slot;
// the last retiring block resets g_done/ticket/finished) so every graph
// replay starts from zeroed state (deterministic).
__device__ unsigned long long g_best[BATCH * NCUE];
__device__ unsigned           g_done[BATCH];
__device__ unsigned           g_ticket;
__device__ unsigned           g_finished;

__device__ __forceinline__ unsigned f2key(float f) {
    unsigned u = __float_as_uint(f);
    return (u & 0x80000000u) ? ~u : (u | 0x80000000u);
}
__device__ __forceinline__ void fma2(unsigned long long& d, unsigned long long a,
                                     unsigned long long b) {
    asm volatile("fma.rn.f32x2 %0, %1, %2, %0;" : "+l"(d) : "l"(a), "l"(b));
}
__device__ __forceinline__ void lds_v2u64(unsigned long long& lo, unsigned long long& hi,
                                          unsigned addr) {
    asm volatile("ld.shared.v2.u64 {%0, %1}, [%2];" : "=l"(lo), "=l"(hi) : "r"(addr));
}
__device__ __forceinline__ void cp16(unsigned dst, const void* src) {
    asm volatile("cp.async.cg.shared.global [%0], [%1], 16;" :: "r"(dst), "l"(src)
                 : "memory");
}

// ---------------------------------------------------------------------------
// Single persistent kernel with CROSS-ITEM PIPELINING. Ticket space:
// [0,1408) argmax tiles (batch-consecutive), [1408,2048) ROI-token items.
// Each block holds a one-deep ticket prefetch; when the next item is also an
// argmax tile, the current mainloop's tail stages issue the next item's
// stages 0-2 into the freed ring slots (uniform wait_group 2 across the
// boundary), so the cp.async engine never drains between items.
// ---------------------------------------------------------------------------
__global__ __launch_bounds__(TPB, 4) void fused_kernel(const float* __restrict__ tokens,
                                                       float* __restrict__ out) {
    __shared__ float4 stage_buf[NBUF][STAGE_F4];        // 32 KB
    __shared__ float  cue_sm[NCUE * D];                 // 15 KB
    __shared__ unsigned long long warp_best[TPB / 32][NCUE];
    __shared__ unsigned sm_item;
    __shared__ int      sm_idx;
    __shared__ float    red4[4];

    const int t    = threadIdx.x;
    const int lane = t & 31;
    const int warp = t >> 5;
    const unsigned sb0 = (unsigned)__cvta_generic_to_shared(&stage_buf[0][0]);

    // Item-invariant staging geometry: instr q (0..3) stages rows
    // R = 32w + 8q + (lane>>2), 16B segment lane&3 (contiguous 512B spans).
    const int seg = lane & 3;
    int      rrow[4];
    unsigned sdst[4];
#pragma unroll
    for (int q = 0; q < 4; q++) {
        const int R = warp * 32 + q * 8 + (lane >> 2);
        rrow[q] = R;
        sdst[q] = sb0 + (unsigned)(R * 64 + ((seg ^ ((R >> 1) & 3)) * 16));
    }
    const unsigned rbase = sb0 + (unsigned)(t * 64);
    const int      sw    = (t >> 1) & 3;
    const unsigned cbase = (unsigned)__cvta_generic_to_shared(cue_sm);

#define ISSUE_FROM(srcarr, stage_in_item, ring_slot)                            \
    do {                                                                        \
        const unsigned _bo = (unsigned)((ring_slot) * STAGE_B);                 \
        const int _go = (stage_in_item) * (DC * 4);                             \
        _Pragma("unroll")                                                       \
        for (int _q = 0; _q < 4; _q++) cp16(sdst[_q] + _bo, (srcarr)[_q] + _go);\
        asm volatile("cp.async.commit_group;" ::: "memory");                    \
    } while (0)

    unsigned cur;
    if (t == 0) sm_item = atomicAdd(&g_ticket, 1u);
    __syncthreads();
    cur = sm_item;
    bool preloaded = false;

    for (;;) {
        if (cur >= (unsigned)NITEMS_ALL) break;
        if (t == 0) sm_item = atomicAdd(&g_ticket, 1u);   // prefetch next ticket

        if (cur < (unsigned)N_AM) {
            // ================= argmax tile item =================
            const int b    = (int)(cur / NTILE);
            const int tile = (int)(cur - (unsigned)(b * NTILE));
            const int p0   = tile * PTILE;
            const float* base  = tokens + (size_t)b * STOK * D;
            const float* patch = base + NCUE * D;

            const char* gsrc[4];
#pragma unroll
            for (int q = 0; q < 4; q++) {
                const int pidx = min(p0 + rrow[q], NPATCH - 1);   // tail clamp
                gsrc[q] = (const char*)(patch + (size_t)pidx * D) + seg * 16;
            }

            if (!preloaded) {
                ISSUE_FROM(gsrc, 0, 0);
                ISSUE_FROM(gsrc, 1, 1);
                ISSUE_FROM(gsrc, 2, 2);
            }

            {   // cues = tokens[b, 0:5, :] (contiguous; L2-resident)
                const float4* cg = (const float4*)base;
                float4* cs = (float4*)cue_sm;
                for (int i = t; i < NCUE * D / 4; i += TPB) cs[i] = cg[i];
            }
            __syncthreads();                    // publishes sm_item + cue_sm

            const unsigned nxt = sm_item;
            const bool pf = (nxt < (unsigned)N_AM);
            const char* ngsrc[4];
            if (pf) {
                const int nb   = (int)(nxt / NTILE);
                const int np0  = (int)(nxt - (unsigned)(nb * NTILE)) * PTILE;
                const float* npatch = tokens + (size_t)nb * STOK * D + NCUE * D;
#pragma unroll
                for (int q = 0; q < 4; q++) {
                    const int pidx = min(np0 + rrow[q], NPATCH - 1);
                    ngsrc[q] = (const char*)(npatch + (size_t)pidx * D) + seg * 16;
                }
            }

            unsigned long long acc[NCUE][2];
#pragma unroll
            for (int c = 0; c < NCUE; c++) { acc[c][0] = 0ull; acc[c][1] = 0ull; }

            for (int s = 0; s < NS; s++) {
                if (pf || s < NS - 2)  asm volatile("cp.async.wait_group 2;" ::: "memory");
                else if (s == NS - 2)  asm volatile("cp.async.wait_group 1;" ::: "memory");
                else                   asm volatile("cp.async.wait_group 0;" ::: "memory");
                __syncwarp();

                const unsigned bo = (unsigned)((s & (NBUF - 1)) * STAGE_B);
                const unsigned cb = cbase + (unsigned)(s * DC * 4);
#pragma unroll
                for (int j = 0; j < F4ROW; j++) {
                    unsigned long long plo, phi;
                    lds_v2u64(plo, phi, rbase + bo + (unsigned)(((j ^ sw) * 16)));
#pragma unroll
                    for (int c = 0; c < NCUE; c++) {
                        unsigned long long qlo, qhi;
                        lds_v2u64(qlo, qhi, cb + (unsigned)(c * D * 4 + j * 16));
                        fma2(acc[c][0], plo, qlo);
                        fma2(acc[c][1], phi, qhi);
                    }
                }
                __syncwarp();                   // reads done before ring reuse
                const int is = s + 3;
                if (is < NS)      ISSUE_FROM(gsrc,  is,      is & (NBUF - 1));
                else if (pf)      ISSUE_FROM(ngsrc, is - NS, is & (NBUF - 1));
            }

            const int pidx = min(p0 + t, NPATCH - 1);
            const unsigned lowbits = 0xFFFFFFFFu - (unsigned)pidx;
            unsigned long long key[NCUE];
#pragma unroll
            for (int c = 0; c < NCUE; c++) {
                float a0 = __uint_as_float((unsigned)(acc[c][0] & 0xFFFFFFFFull));
                float a1 = __uint_as_float((unsigned)(acc[c][0] >> 32));
                float a2 = __uint_as_float((unsigned)(acc[c][1] & 0xFFFFFFFFull));
                float a3 = __uint_as_float((unsigned)(acc[c][1] >> 32));
                float sim = (a0 + a1) + (a2 + a3);
                key[c] = ((unsigned long long)f2key(sim) << 32) | lowbits;
            }
#pragma unroll
            for (int c = 0; c < NCUE; c++)
#pragma unroll
                for (int o = 16; o; o >>= 1) {
                    unsigned long long other = __shfl_xor_sync(0xffffffffu, key[c], o);
                    key[c] = (other > key[c]) ? other : key[c];
                }
            if (lane == 0)
#pragma unroll
                for (int c = 0; c < NCUE; c++) warp_best[warp][c] = key[c];
            __syncthreads();
            if (t < NCUE) {
                unsigned long long m = warp_best[0][t];
#pragma unroll
                for (int w = 1; w < TPB / 32; w++)
                    m = (warp_best[w][t] > m) ? warp_best[w][t] : m;
                atomicMax(&g_best[b * NCUE + t], m);
                __threadfence();                // publish before g_done bump
            }
            __syncthreads();
            if (t == 0) atomicAdd(&g_done[b], 1u);

            // tile-0 block emits the 5 cue-token outputs from cue_sm
            if (tile == 0) {
#pragma unroll 1
                for (int tk = 0; tk < NCUE; tk++) {
                    float v[6];
#pragma unroll
                    for (int j = 0; j < 6; j++) v[j] = cue_sm[tk * D + t + 128 * j];
                    float ss = 0.0f;
#pragma unroll
                    for (int j = 0; j < 6; j++) ss += v[j] * v[j];
#pragma unroll
                    for (int o = 16; o > 0; o >>= 1)
                        ss += __shfl_xor_sync(0xffffffffu, ss, o);
                    if (lane == 0) red4[warp] = ss;
                    __syncthreads();
                    float tot = red4[0] + red4[1] + red4[2] + red4[3];
                    __syncthreads();
                    const float scale = 1.0f / fmaxf(sqrtf(tot), EPSN);
                    float* orow = out + ((size_t)b * 10 + tk) * D;
#pragma unroll
                    for (int j = 0; j < 6; j++) orow[t + 128 * j] = v[j] * scale;
                }
            }

            cur = nxt;
            preloaded = pf;
        } else {
            // ================= ROI-token gather item =================
            const unsigned gid = cur - (unsigned)N_AM;
            const int b = (int)(gid / NCUE);
            const int c = (int)(gid - (unsigned)(b * NCUE));

            if (t == 0) {
                unsigned d;
                do {
                    asm volatile("ld.acquire.gpu.u32 %0, [%1];"
                                 : "=r"(d) : "l"(&g_done[b]) : "memory");
                    if (d < (unsigned)NTILE) __nanosleep(200);
                } while (d < (unsigned)NTILE);
                const unsigned long long key = atomicAdd(&g_best[b * NCUE + c], 0ull);
                sm_idx = (int)(0xFFFFFFFFu - (unsigned)(key & 0xFFFFFFFFull));
                g_best[b * NCUE + c] = 0ull;    // reset for next replay
            }
            __syncthreads();                    // publishes sm_idx + sm_item

            const unsigned nxt = sm_item;
            const int idx = sm_idx;
            const int h = idx / G, w = idx % G;
            const float* patch = tokens + (size_t)b * STOK * D + NCUE * D;

            const float* prow[9];
            float msk[9];
            float cnt = 0.0f;
#pragma unroll
            for (int dr = -1; dr <= 1; dr++)
#pragma unroll
                for (int dc2 = -1; dc2 <= 1; dc2++) {
                    const int k  = (dr + 1) * 3 + (dc2 + 1);
                    const int rr = h + dr, cc = w + dc2;
                    const bool ok = (rr >= 0) & (rr < G) & (cc >= 0) & (cc < G);
                    const int rcl = min(max(rr, 0), G - 1);
                    const int ccl = min(max(cc, 0), G - 1);
                    prow[k] = patch + (size_t)(rcl * G + ccl) * D;
                    msk[k]  = ok ? 1.0f : 0.0f;
                    cnt += msk[k];
                }
            const float inv = 1.0f / cnt;

            float v[6];
#pragma unroll
            for (int j = 0; j < 6; j++) v[j] = 0.0f;
#pragma unroll
            for (int k = 0; k < 9; k++)
#pragma unroll
                for (int j = 0; j < 6; j++)
                    v[j] = fmaf(msk[k], prow[k][t + 128 * j], v[j]);
#pragma unroll
            for (int j = 0; j < 6; j++) v[j] *= inv;

            float ss = 0.0f;
#pragma unroll
            for (int j = 0; j < 6; j++) ss += v[j] * v[j];
#pragma unroll
            for (int o = 16; o > 0; o >>= 1) ss += __shfl_xor_sync(0xffffffffu, ss, o);
            if (lane == 0) red4[warp] = ss;
            __syncthreads();
            const float tot = red4[0] + red4[1] + red4[2] + red4[3];
            __syncthreads();
            const float scale = 1.0f / fmaxf(sqrtf(tot), EPSN);

            float* orow = out + ((size_t)b * 10 + NCUE + c) * D;
#pragma unroll
            for (int j = 0; j < 6; j++) orow[t + 128 * j] = v[j] * scale;

            cur = nxt;
            preloaded = false;
        }
    }
#undef ISSUE_FROM

    // retire: last block resets counters for the next graph replay
    if (t == 0) {
        __threadfence();
        const unsigned prev = atomicAdd(&g_finished, 1u);
        if (prev == (unsigned)(NBLK - 1)) {
            for (int i = 0; i < BATCH; i++) g_done[i] = 0u;
            g_ticket   = 0u;
            g_finished = 0u;
        }
    }
}

extern "C" void kernel_launch(void* const* d_in, const int* in_sizes, int n_in,
                              void* d_out, int out_size) {
    const float* tokens = (const float*)d_in[0];
    float* out = (float*)d_out;

    fused_kernel<<<NBLK, TPB>>>(tokens, out);
}